// round 8
// baseline (speedup 1.0000x reference)
#include <cuda_runtime.h>
#include <cuda_bf16.h>
#include <math.h>

#define NB 16
#define NT 8
#define LT 2048
#define NEP 920
#define NH 24
#define HD 32
#define DS 128
#define DM 192
#define KV 576      // virtual K for bf16x3

__device__ float g_projR[(size_t)NB*NT*128*NEP];
__device__ float g_y[(size_t)NB*LT*HD];
__device__ float g_B[(size_t)NB*LT*DS];
__device__ float g_w[(size_t)NB*NH*LT];          // [b][h][l]
__device__ float g_tail2[NB*NH*NT];
__device__ float g_wsum[NB*NT*NH];
__device__ float g_Zsub[NB*8*2*4096];
__device__ float g_C[NB*8*4096];
__device__ float g_S[NB*8*4096];
__device__ float g_part[8*128*100];
__device__ float g_peproj[8*NEP];
__device__ float g_xc[8*896];
__device__ float g_dtpad[8*NH];
__device__ float g_ldpad[8*NH];
__device__ __nv_bfloat16 g_Bcat[1024*KV];                  // [e][hi|lo|hi]
__device__ __nv_bfloat16 g_Acat[(size_t)NB*NT*128*384];    // [row][hi192|lo192]

__device__ __forceinline__ float softplus_f(float z){
    return log1pf(expf(-fabsf(z))) + fmaxf(z, 0.f);
}
__device__ __forceinline__ float silu_f(float v){
    return v / (1.f + expf(-v));
}
__device__ __forceinline__ int wrow_of(int ce){
    return (ce < 896) ? (768 + ce) : (896 + ce);
}
__device__ __forceinline__ float ld_proj(int b, int l, int e){
    int r = l & 255;
    if (r >= 128) return g_peproj[(l >> 8)*NEP + e];
    return g_projR[(((size_t)b*NT + (l >> 8))*128 + r)*NEP + e];
}

// ---- positional encoding rows projected through W ----
__global__ void k_peproj(const float* __restrict__ in_proj_w){
    __shared__ float pe[DM];
    int t = blockIdx.x;
    int tid = threadIdx.x;
    if (tid < DM){
        float expo = -(float)(tid & ~1) * (logf(10000.0f)/(float)DM);
        float div = expf(expo);
        float ang = (float)t * div;
        pe[tid] = (tid & 1) ? cosf(ang) : sinf(ang);
    }
    __syncthreads();
    for (int e = tid; e < NEP; e += blockDim.x){
        const float* wr = in_proj_w + (size_t)wrow_of(e)*DM;
        float s = 0.f;
        for (int d = 0; d < DM; d++) s += pe[d]*wr[d];
        g_peproj[t*NEP + e] = s;
    }
}

// ---- const-pad conv+silu per t, pad dt/logdA per (t,h) ----
__global__ void k_xc(const float* __restrict__ conv_w, const float* __restrict__ conv_b,
                     const float* __restrict__ dt_bias, const float* __restrict__ A_log){
    int t = blockIdx.x;
    int tid = threadIdx.x;
    for (int c = tid; c < 896; c += 256){
        float4 wv = *(const float4*)(conv_w + (size_t)c*4);
        float v = conv_b[c] + g_peproj[t*NEP + c]*(wv.x + wv.y + wv.z + wv.w);
        g_xc[t*896 + c] = silu_f(v);
    }
    if (tid < NH){
        float z = g_peproj[t*NEP + 896 + tid] + dt_bias[tid];
        float dt = softplus_f(z);
        g_dtpad[t*NH + tid] = dt;
        g_ldpad[t*NH + tid] = -expf(A_log[tid])*dt;
    }
}

// ---- pack weight matrix into bf16x3 catalog [e][hi|lo|hi] ----
__global__ void k_bprep(const float* __restrict__ in_proj_w){
    int e = blockIdx.x, k = threadIdx.x;
    __nv_bfloat16 hi, lo;
    if (e < NEP){
        float w = in_proj_w[(size_t)wrow_of(e)*DM + k];
        hi = __float2bfloat16(w);
        lo = __float2bfloat16(w - __bfloat162float(hi));
    } else {
        hi = __float2bfloat16(0.f); lo = hi;
    }
    g_Bcat[(size_t)e*KV + k]        = hi;
    g_Bcat[(size_t)e*KV + 192 + k]  = lo;
    g_Bcat[(size_t)e*KV + 384 + k]  = hi;
}

// ---- pre-convert activations: fp32 -> [hi192|lo192] bf16 per row ----
__global__ void k_aprep(const float* __restrict__ inputs){
    int row = blockIdx.x;
    int k = threadIdx.x;
    int bt = row >> 7, r = row & 127;
    float v = inputs[((size_t)bt*129 + 1 + r)*DM + k];
    __nv_bfloat16 hi = __float2bfloat16(v);
    __nv_bfloat16 lo = __float2bfloat16(v - __bfloat162float(hi));
    g_Acat[(size_t)row*384 + k]       = hi;
    g_Acat[(size_t)row*384 + 192 + k] = lo;
}

// ---- main GEMM on tensor pipe: cp.async staging + ldmatrix + mma.sync ----
#define ASTR 40
__global__ void __launch_bounds__(256) k_gemm(){
    int bt = blockIdx.x;
    int t = bt & 7;
    int n0 = blockIdx.y * 128;
    __shared__ __nv_bfloat16 As[2][128][ASTR];
    __shared__ __nv_bfloat16 Bs[2][128][ASTR];
    int tid = threadIdx.x;
    int srow = tid >> 1, half = tid & 1;
    const __nv_bfloat16* Arow = g_Acat + ((size_t)bt*128 + srow)*384;
    const __nv_bfloat16* Brow = g_Bcat + (size_t)(n0 + srow)*KV;

    int wid = tid >> 5, lane = tid & 31;
    int wm = (wid & 1)*64, wn = (wid >> 1)*32;
    int gid = lane >> 2, tig = lane & 3;
    int lrow = lane & 15;               // ldmatrix row-within-16
    int lcol = (lane >> 4) * 8;         // ldmatrix k half

    float acc[4][4][4];
    #pragma unroll
    for (int i = 0; i < 4; i++)
        #pragma unroll
        for (int j = 0; j < 4; j++)
            #pragma unroll
            for (int q = 0; q < 4; q++) acc[i][j][q] = 0.f;

    auto stage = [&](int j, int buf){
        int aoff = (j < 6) ? 32*j : 32*j - 192;
        int boff = 32*j;
        unsigned da = (unsigned)__cvta_generic_to_shared(&As[buf][srow][half*16]);
        unsigned db = (unsigned)__cvta_generic_to_shared(&Bs[buf][srow][half*16]);
        const __nv_bfloat16* pa = Arow + aoff + half*16;
        const __nv_bfloat16* pb = Brow + boff + half*16;
        asm volatile("cp.async.cg.shared.global [%0], [%1], 16;" :: "r"(da), "l"(pa));
        asm volatile("cp.async.cg.shared.global [%0], [%1], 16;" :: "r"(da + 16u), "l"(pa + 8));
        asm volatile("cp.async.cg.shared.global [%0], [%1], 16;" :: "r"(db), "l"(pb));
        asm volatile("cp.async.cg.shared.global [%0], [%1], 16;" :: "r"(db + 16u), "l"(pb + 8));
    };

    stage(0, 0);
    asm volatile("cp.async.commit_group;");

    #pragma unroll 1
    for (int j = 0; j < 18; j++){
        int cur = j & 1;
        if (j + 1 < 18){
            stage(j + 1, cur ^ 1);
            asm volatile("cp.async.commit_group;");
            asm volatile("cp.async.wait_group 1;");
        } else {
            asm volatile("cp.async.wait_group 0;");
        }
        __syncthreads();
        #pragma unroll
        for (int ks = 0; ks < 2; ks++){
            int k0 = ks*16;
            unsigned aF[4][4], bF[4][2];
            #pragma unroll
            for (int mt = 0; mt < 4; mt++){
                unsigned addr = (unsigned)__cvta_generic_to_shared(
                    &As[cur][wm + mt*16 + lrow][k0 + lcol]);
                asm volatile("ldmatrix.sync.aligned.m8n8.x4.shared.b16 {%0,%1,%2,%3}, [%4];"
                    : "=r"(aF[mt][0]), "=r"(aF[mt][1]), "=r"(aF[mt][2]), "=r"(aF[mt][3])
                    : "r"(addr));
            }
            #pragma unroll
            for (int np = 0; np < 2; np++){
                unsigned r0, r1, r2, r3;
                unsigned addr = (unsigned)__cvta_generic_to_shared(
                    &Bs[cur][wn + np*16 + lrow][k0 + lcol]);
                asm volatile("ldmatrix.sync.aligned.m8n8.x4.shared.b16 {%0,%1,%2,%3}, [%4];"
                    : "=r"(r0), "=r"(r1), "=r"(r2), "=r"(r3) : "r"(addr));
                bF[2*np][0] = r0; bF[2*np+1][0] = r1;
                bF[2*np][1] = r2; bF[2*np+1][1] = r3;
            }
            #pragma unroll
            for (int mt = 0; mt < 4; mt++)
                #pragma unroll
                for (int nt = 0; nt < 4; nt++){
                    asm volatile(
                        "mma.sync.aligned.m16n8k16.row.col.f32.bf16.bf16.f32 "
                        "{%0,%1,%2,%3}, {%4,%5,%6,%7}, {%8,%9}, {%0,%1,%2,%3};"
                        : "+f"(acc[mt][nt][0]), "+f"(acc[mt][nt][1]),
                          "+f"(acc[mt][nt][2]), "+f"(acc[mt][nt][3])
                        : "r"(aF[mt][0]), "r"(aF[mt][1]), "r"(aF[mt][2]), "r"(aF[mt][3]),
                          "r"(bF[nt][0]), "r"(bF[nt][1]));
                }
        }
        __syncthreads();
    }

    // epilogue: + PE bias, store real rows (e < 920)
    #pragma unroll
    for (int mt = 0; mt < 4; mt++){
        #pragma unroll
        for (int nt = 0; nt < 4; nt++){
            int e = n0 + wn + nt*8 + tig*2;
            if (e >= NEP) continue;
            float b0 = g_peproj[t*NEP + e];
            float b1 = g_peproj[t*NEP + e + 1];
            int r0 = wm + mt*16 + gid;
            float* d0 = g_projR + ((size_t)bt*128 + r0)*NEP + e;
            float* d1 = g_projR + ((size_t)bt*128 + r0 + 8)*NEP + e;
            float2 v0 = make_float2(acc[mt][nt][0] + b0, acc[mt][nt][1] + b1);
            float2 v1 = make_float2(acc[mt][nt][2] + b0, acc[mt][nt][3] + b1);
            *(float2*)d0 = v0;
            *(float2*)d1 = v1;
        }
    }
}

// ---- per-(b,h) scan: parallel within-chunk suffix scan, fp64 across chunks ----
__global__ void __launch_bounds__(128) k_scan(const float* __restrict__ dt_bias,
                                              const float* __restrict__ A_log){
    int b = blockIdx.x / NH, h = blockIdx.x % NH;
    int tid = threadIdx.x;
    float db = dt_bias[h];
    float nA = expf(A_log[h]);
    float dtv[8], ldv[8], v[8];
    #pragma unroll
    for (int t = 0; t < 8; t++){
        float z = g_projR[(((size_t)(b*8 + t))*128 + tid)*NEP + 896 + h] + db;
        float dt = softplus_f(z);
        dtv[t] = dt;
        ldv[t] = -nA*dt;
        v[t] = ldv[t];
    }
    __shared__ float sm[128][9];
    #pragma unroll
    for (int off = 1; off < 128; off <<= 1){
        __syncthreads();
        #pragma unroll
        for (int t = 0; t < 8; t++) sm[tid][t] = v[t];
        __syncthreads();
        if (tid + off < 128){
            #pragma unroll
            for (int t = 0; t < 8; t++) v[t] += sm[tid + off][t];
        }
    }
    float excl[8];
    #pragma unroll
    for (int t = 0; t < 8; t++) excl[t] = v[t] - ldv[t];
    __shared__ float totsh[8];
    if (tid == 0){
        #pragma unroll
        for (int t = 0; t < 8; t++) totsh[t] = v[t];
    }
    __syncthreads();
    float ldp[8], dtp[8];
    #pragma unroll
    for (int t = 0; t < 8; t++){ ldp[t] = g_ldpad[t*NH + h]; dtp[t] = g_dtpad[t*NH + h]; }
    double Gt[8];
    Gt[7] = 0.0;
    #pragma unroll
    for (int t = 6; t >= 0; t--)
        Gt[t] = Gt[t+1] + (double)totsh[t+1] + 128.0*(double)ldp[t+1];
    size_t wbase = (size_t)(b*NH + h)*LT;
    #pragma unroll
    for (int t = 0; t < 8; t++){
        float tail = excl[t] + 128.f*ldp[t] + (float)Gt[t];
        g_w[wbase + t*256 + tid] = dtv[t]*expf(tail);
        if (tid == 2) g_tail2[(b*NH + h)*NT + t] = tail;
    }
    if (tid < 16){
        int s = 128 + tid;
        #pragma unroll
        for (int t = 0; t < 8; t++)
            g_w[wbase + t*256 + s] = dtp[t]*expf((float)(255 - s)*ldp[t] + (float)Gt[t]);
    }
    if (tid < 8){
        int t = tid;
        double ld = (double)ldp[t];
        double geo = expm1(125.0*ld)/expm1(ld);
        g_wsum[(b*8 + t)*NH + h] = (float)((double)dtp[t]*exp(Gt[t])*geo);
    }
}

// ---- fused conv(4)+silu + head-combine, register rolling windows, 16 l per block ----
__global__ void __launch_bounds__(256) k_convy(const float* __restrict__ conv_w,
                                               const float* __restrict__ conv_b){
    int blk = blockIdx.x;
    int bt = blk / 9, j9 = blk - bt*9;
    int b = bt >> 3, t = bt & 7;
    int l0 = t*256 + j9*16;
    int tid = threadIdx.x;
    __shared__ float wsm[16][NH];
    __shared__ float ypart[256][17];
    for (int i = tid; i < 16*NH; i += 256){
        int l = i / NH, h = i - l*NH;
        wsm[l][h] = g_w[((size_t)(b*NH + h))*LT + l0 + l];
    }
    int c0 = tid, c1 = tid + 256, c2 = tid + 512, cB = 768 + (tid & 127);
    float4 w0 = *(const float4*)(conv_w + (size_t)c0*4);
    float4 w1 = *(const float4*)(conv_w + (size_t)c1*4);
    float4 w2 = *(const float4*)(conv_w + (size_t)c2*4);
    float cb0 = conv_b[c0], cb1 = conv_b[c1], cb2 = conv_b[c2];
    float4 wB = make_float4(0.f,0.f,0.f,0.f); float cbB = 0.f;
    bool doB = (tid < 128);
    if (doB){ wB = *(const float4*)(conv_w + (size_t)cB*4); cbB = conv_b[cB]; }
    int h0 = tid >> 5;
    float u0[4], u1[4], u2[4], uB[4];
    #pragma unroll
    for (int k = 1; k < 4; k++){
        int gl = l0 - 4 + k;
        bool ok = (gl >= 0);
        u0[k] = ok ? ld_proj(b, gl, c0) : 0.f;
        u1[k] = ok ? ld_proj(b, gl, c1) : 0.f;
        u2[k] = ok ? ld_proj(b, gl, c2) : 0.f;
        uB[k] = (ok && doB) ? ld_proj(b, gl, cB) : 0.f;
    }
    __syncthreads();
    float yl[16];
    #pragma unroll
    for (int j = 0; j < 16; j++){
        int gl = l0 + j;
        u0[0]=u0[1]; u0[1]=u0[2]; u0[2]=u0[3]; u0[3]=ld_proj(b, gl, c0);
        u1[0]=u1[1]; u1[1]=u1[2]; u1[2]=u1[3]; u1[3]=ld_proj(b, gl, c1);
        u2[0]=u2[1]; u2[1]=u2[2]; u2[2]=u2[3]; u2[3]=ld_proj(b, gl, c2);
        uB[0]=uB[1]; uB[1]=uB[2]; uB[2]=uB[3]; uB[3]=doB ? ld_proj(b, gl, cB) : 0.f;
        float v0 = cb0 + u0[0]*w0.x + u0[1]*w0.y + u0[2]*w0.z + u0[3]*w0.w;
        float v1 = cb1 + u1[0]*w1.x + u1[1]*w1.y + u1[2]*w1.z + u1[3]*w1.w;
        float v2 = cb2 + u2[0]*w2.x + u2[1]*w2.y + u2[2]*w2.z + u2[3]*w2.w;
        yl[j] = silu_f(v0)*wsm[j][h0] + silu_f(v1)*wsm[j][h0+8] + silu_f(v2)*wsm[j][h0+16];
        if (doB){
            float vB = cbB + uB[0]*wB.x + uB[1]*wB.y + uB[2]*wB.z + uB[3]*wB.w;
            g_B[((size_t)b*LT + gl)*DS + (tid & 127)] = silu_f(vB);
        }
    }
    #pragma unroll
    for (int j = 0; j < 16; j++) ypart[tid][j] = yl[j];
    __syncthreads();
    #pragma unroll
    for (int half = 0; half < 2; half++){
        int l = half*8 + (tid >> 5), p = tid & 31;
        float y = 0.f;
        #pragma unroll
        for (int g = 0; g < 8; g++) y += ypart[g*32 + p][l];
        g_y[((size_t)b*LT + l0 + l)*HD + p] = y;
    }
}

// ---- segment outer products over [256t+3, 256t+131), 2 subs of 64 ----
__global__ void __launch_bounds__(128) k_seg(){
    int idx = blockIdx.x;
    int b = idx >> 4, t = (idx >> 1) & 7, sub = idx & 1;
    int lbeg = t*256 + 3 + sub*64;
    int lend = lbeg + 64;
    int n = threadIdx.x;
    __shared__ float ysm[8][HD];
    float acc[HD];
    #pragma unroll
    for (int p = 0; p < HD; p++) acc[p] = 0.f;
    for (int l8 = lbeg; l8 < lend; l8 += 8){
        __syncthreads();
        for (int i = n; i < 8*HD; i += 128)
            ysm[i >> 5][i & 31] = g_y[((size_t)b*LT + l8 + (i >> 5))*HD + (i & 31)];
        __syncthreads();
        #pragma unroll
        for (int j = 0; j < 8; j++){
            float Bn = g_B[((size_t)b*LT + l8 + j)*DS + n];
            #pragma unroll
            for (int p = 0; p < HD; p++) acc[p] += ysm[j][p]*Bn;
        }
    }
    if (sub == 1 && t < 7){
        int lc = (t + 1)*256;
        __syncthreads();
        for (int i = n; i < 3*HD; i += 128)
            ysm[i >> 5][i & 31] = g_y[((size_t)b*LT + lc + (i >> 5))*HD + (i & 31)];
        __syncthreads();
        #pragma unroll
        for (int j = 0; j < 3; j++){
            float Bn = g_B[((size_t)b*LT + lc + j)*DS + n];
            #pragma unroll
            for (int p = 0; p < HD; p++) acc[p] += ysm[j][p]*Bn;
        }
    }
    float* Z = g_Zsub + (size_t)idx*4096;
    #pragma unroll
    for (int p = 0; p < HD; p++) Z[p*DS + n] = acc[p];
}

// ---- per-(b,t) 3-position boundary correction ----
__global__ void __launch_bounds__(128) k_bdry(const float* __restrict__ conv_w,
                                              const float* __restrict__ conv_b,
                                              const float* __restrict__ dt_bias,
                                              const float* __restrict__ A_log){
    int b = blockIdx.x >> 3, t = blockIdx.x & 7;
    int tid = threadIdx.x;
    __shared__ float xsb[3][896];
    __shared__ float dtb[3][NH], ldb[3][NH], wjs[3][NH];
    __shared__ float ysh[3][HD];
    for (int c = tid; c < 896; c += 128){
        float4 wv = *(const float4*)(conv_w + (size_t)c*4);
        float w[4] = {wv.x, wv.y, wv.z, wv.w};
        float cb = conv_b[c];
        #pragma unroll
        for (int j = 0; j < 3; j++){
            float v = cb;
            for (int k = 3-j; k <= 3; k++)
                v += g_projR[(((size_t)(b*NT + t))*128 + (j - 3 + k))*NEP + c]*w[k];
            xsb[j][c] = silu_f(v);
        }
    }
    if (tid < NH){
        int h = tid;
        float db = dt_bias[h], nA = expf(A_log[h]);
        for (int j = 0; j < 3; j++){
            float z = g_projR[(((size_t)(b*NT + t))*128 + j)*NEP + 896 + h] + db;
            float dt = softplus_f(z);
            dtb[j][h] = dt; ldb[j][h] = -nA*dt;
        }
    }
    __syncthreads();
    if (tid < NH){
        int h = tid;
        float t2 = g_tail2[(b*NH + h)*NT + t];
        wjs[2][h] = dtb[2][h]*expf(t2);
        float t1 = t2 + ldb[2][h];
        wjs[1][h] = dtb[1][h]*expf(t1);
        float t0 = t1 + ldb[1][h];
        wjs[0][h] = dtb[0][h]*expf(t0);
    }
    __syncthreads();
    if (tid < 96){
        int j = tid >> 5, p = tid & 31;
        float y = 0.f;
        #pragma unroll
        for (int h = 0; h < NH; h++) y += wjs[j][h]*xsb[j][h*HD + p];
        ysh[j][p] = y;
    }
    __syncthreads();
    int n = tid;
    float B0 = xsb[0][768+n], B1 = xsb[1][768+n], B2 = xsb[2][768+n];
    float* C = g_C + (size_t)blockIdx.x*4096;
    #pragma unroll
    for (int p = 0; p < HD; p++)
        C[p*DS + n] = ysh[0][p]*B0 + ysh[1][p]*B1 + ysh[2][p]*B2;
}

// ---- suffix-sum segments + rank-1 pad term + boundary corrections ----
__global__ void __launch_bounds__(256) k_finalS(){
    int b = blockIdx.x;
    int tid = threadIdx.x;
    __shared__ float ysh[8][32];
    {
        int t = tid >> 5, p = tid & 31;
        float s = 0.f;
        #pragma unroll
        for (int h = 0; h < NH; h++)
            s += g_wsum[(b*8 + t)*NH + h]*g_xc[t*896 + h*HD + p];
        ysh[t][p] = s;
    }
    __syncthreads();
    int i = blockIdx.y*256 + tid;
    int p = i >> 7, n = i & 127;
    float run = 0.f;
    for (int t = 7; t >= 0; t--){
        size_t zb = ((size_t)(b*8 + t))*2*4096 + i;
        run += g_Zsub[zb] + g_Zsub[zb + 4096] + ysh[t][p]*g_xc[t*896 + 768 + n];
        g_S[(size_t)(b*8 + t)*4096 + i] = run + g_C[(size_t)(b*8 + t)*4096 + i];
    }
}

// ---- classifier GEMM, split-K ----
__global__ void __launch_bounds__(256) k_cls(const float* __restrict__ cls_w){
    int m0 = blockIdx.x*32, n0 = blockIdx.y*32;
    int kz0 = blockIdx.z*512;
    __shared__ float As[32][33], Bs[32][33];
    int tid = threadIdx.x;
    int tx = tid & 15, ty = tid >> 4;
    int am = tid >> 3, aq = (tid & 7)*4;
    float acc00 = 0, acc01 = 0, acc10 = 0, acc11 = 0;
    bool bvalid = (n0 + am) < 100;
    for (int k0 = kz0; k0 < kz0 + 512; k0 += 32){
        float4 av = *reinterpret_cast<const float4*>(g_S + (size_t)(m0 + am)*4096 + k0 + aq);
        float4 bv = bvalid ? *reinterpret_cast<const float4*>(cls_w + (size_t)(n0 + am)*4096 + k0 + aq)
                           : make_float4(0.f, 0.f, 0.f, 0.f);
        __syncthreads();
        As[am][aq+0] = av.x; As[am][aq+1] = av.y; As[am][aq+2] = av.z; As[am][aq+3] = av.w;
        Bs[aq+0][am] = bv.x; Bs[aq+1][am] = bv.y; Bs[aq+2][am] = bv.z; Bs[aq+3][am] = bv.w;
        __syncthreads();
        #pragma unroll
        for (int k = 0; k < 32; k++){
            float a0 = As[ty*2][k],   a1 = As[ty*2+1][k];
            float b0 = Bs[k][tx*2],   b1 = Bs[k][tx*2+1];
            acc00 += a0*b0; acc01 += a0*b1; acc10 += a1*b0; acc11 += a1*b1;
        }
    }
    int m = m0 + ty*2, n = n0 + tx*2;
    float* P = g_part + (size_t)blockIdx.z*12800;
    if (n < 100)    { P[m*100 + n]     = acc00; P[(m+1)*100 + n]     = acc10; }
    if (n + 1 < 100){ P[m*100 + n + 1] = acc01; P[(m+1)*100 + n + 1] = acc11; }
}

__global__ void k_out(const float* __restrict__ cls_b, float* __restrict__ out){
    int i = blockIdx.x*blockDim.x + threadIdx.x;
    if (i >= 12800) return;
    int k = i % 100;
    float s = cls_b[k];
    #pragma unroll
    for (int z = 0; z < 8; z++) s += g_part[z*12800 + i];
    out[i] = s;
}

extern "C" void kernel_launch(void* const* d_in, const int* in_sizes, int n_in,
                              void* d_out, int out_size){
    const float* inputs    = (const float*)d_in[0];
    const float* in_proj_w = (const float*)d_in[1];
    const float* conv_w    = (const float*)d_in[2];
    const float* conv_b    = (const float*)d_in[3];
    const float* dt_bias   = (const float*)d_in[4];
    const float* A_log     = (const float*)d_in[5];
    const float* cls_w     = (const float*)d_in[6];
    const float* cls_b     = (const float*)d_in[7];
    float* out = (float*)d_out;

    k_peproj<<<8, 256>>>(in_proj_w);
    k_xc<<<8, 256>>>(conv_w, conv_b, dt_bias, A_log);
    k_bprep<<<1024, 192>>>(in_proj_w);
    k_aprep<<<16384, 192>>>(inputs);
    k_gemm<<<dim3(128, 8), 256>>>();
    k_scan<<<16*24, 128>>>(dt_bias, A_log);
    k_convy<<<128*9, 256>>>(conv_w, conv_b);
    k_seg<<<256, 128>>>();
    k_bdry<<<128, 128>>>(conv_w, conv_b, dt_bias, A_log);
    k_finalS<<<dim3(16, 16), 256>>>();
    k_cls<<<dim3(4, 4, 8), 256>>>(cls_w);
    k_out<<<50, 256>>>(cls_b, out);
}

// round 11
// speedup vs baseline: 1.3928x; 1.3928x over previous
#include <cuda_runtime.h>
#include <cuda_bf16.h>
#include <math.h>

#define NB 16
#define NT 8
#define LT 2048
#define NEP 920
#define WTS 1024
#define NH 24
#define HD 32
#define DS 128
#define DM 192

__device__ float g_projR[(size_t)NB*NT*128*NEP];
__device__ float g_y[(size_t)NB*LT*HD];
__device__ float g_B[(size_t)NB*LT*DS];
__device__ float g_w[(size_t)NB*NH*LT];          // [b][h][l]
__device__ float g_tail2[NB*NH*NT];
__device__ float g_wsum[NB*NT*NH];
__device__ float g_Zsub[NB*8*2*4096];
__device__ float g_C[NB*8*4096];
__device__ float g_S[NB*8*4096];
__device__ float g_part[8*128*100];
__device__ float g_Wt[192*WTS];
__device__ float g_peproj[8*NEP];
__device__ float g_xc[8*896];
__device__ float g_dtpad[8*NH];
__device__ float g_ldpad[8*NH];

__device__ __forceinline__ float softplus_f(float z){
    return log1pf(expf(-fabsf(z))) + fmaxf(z, 0.f);
}
__device__ __forceinline__ float silu_f(float v){
    return v / (1.f + expf(-v));
}
__device__ __forceinline__ int wrow_of(int ce){
    return (ce < 896) ? (768 + ce) : (896 + ce);
}
__device__ __forceinline__ float ld_proj(int b, int l, int e){
    int r = l & 255;
    if (r >= 128) return g_peproj[(l >> 8)*NEP + e];
    return g_projR[(((size_t)b*NT + (l >> 8))*128 + r)*NEP + e];
}

// ---- transpose W (needed cols only) into [k][e] with zero pad to WTS ----
__global__ void k_wt(const float* __restrict__ in_proj_w){
    int i = blockIdx.x*blockDim.x + threadIdx.x;
    if (i >= 192*WTS) return;
    int k = i / WTS, e = i % WTS;
    g_Wt[i] = (e < NEP) ? in_proj_w[(size_t)wrow_of(e)*DM + k] : 0.f;
}

// ---- positional encoding rows projected through W ----
__global__ void k_peproj(const float* __restrict__ in_proj_w){
    __shared__ float pe[DM];
    int t = blockIdx.x;
    int tid = threadIdx.x;
    if (tid < DM){
        float expo = -(float)(tid & ~1) * (logf(10000.0f)/(float)DM);
        float div = expf(expo);
        float ang = (float)t * div;
        pe[tid] = (tid & 1) ? cosf(ang) : sinf(ang);
    }
    __syncthreads();
    for (int e = tid; e < NEP; e += blockDim.x){
        const float* wr = in_proj_w + (size_t)wrow_of(e)*DM;
        float s = 0.f;
        for (int d = 0; d < DM; d++) s += pe[d]*wr[d];
        g_peproj[t*NEP + e] = s;
    }
}

// ---- const-pad conv+silu per t, pad dt/logdA per (t,h) ----
__global__ void k_xc(const float* __restrict__ conv_w, const float* __restrict__ conv_b,
                     const float* __restrict__ dt_bias, const float* __restrict__ A_log){
    int t = blockIdx.x;
    int tid = threadIdx.x;
    for (int c = tid; c < 896; c += 256){
        float4 wv = *(const float4*)(conv_w + (size_t)c*4);
        float v = conv_b[c] + g_peproj[t*NEP + c]*(wv.x + wv.y + wv.z + wv.w);
        g_xc[t*896 + c] = silu_f(v);
    }
    if (tid < NH){
        float z = g_peproj[t*NEP + 896 + tid] + dt_bias[tid];
        float dt = softplus_f(z);
        g_dtpad[t*NH + tid] = dt;
        g_ldpad[t*NH + tid] = -expf(A_log[tid])*dt;
    }
}

// ---- main GEMM: fp32 SIMT 128x128 tile, 8x8 per thread, double-buffered ----
__global__ void __launch_bounds__(256, 2) k_gemm(const float* __restrict__ inputs){
    int bt = blockIdx.x;
    int t = bt & 7;
    int e0 = blockIdx.y * 128;
    const float* A = inputs + ((size_t)bt*129 + 1)*DM;
    __shared__ float As[2][16][128];
    __shared__ float Bs[2][16][128];
    int tid = threadIdx.x;
    int am = tid & 127, kq = (tid >> 7) * 8;
    int bk = tid >> 5,  bj = (tid & 31) * 4;
    int ty = tid >> 4,  tx = tid & 15;
    float acc[8][8];
    #pragma unroll
    for (int i = 0; i < 8; i++)
        #pragma unroll
        for (int j = 0; j < 8; j++) acc[i][j] = 0.f;

    float4 ra0, ra1, rb0, rb1;
    ra0 = *(const float4*)(A + (size_t)am*DM + kq);
    ra1 = *(const float4*)(A + (size_t)am*DM + kq + 4);
    rb0 = *(const float4*)(g_Wt + (size_t)bk*WTS + e0 + bj);
    rb1 = *(const float4*)(g_Wt + (size_t)(bk + 8)*WTS + e0 + bj);
    As[0][kq+0][am] = ra0.x; As[0][kq+1][am] = ra0.y; As[0][kq+2][am] = ra0.z; As[0][kq+3][am] = ra0.w;
    As[0][kq+4][am] = ra1.x; As[0][kq+5][am] = ra1.y; As[0][kq+6][am] = ra1.z; As[0][kq+7][am] = ra1.w;
    *(float4*)&Bs[0][bk][bj]     = rb0;
    *(float4*)&Bs[0][bk+8][bj]   = rb1;
    __syncthreads();

    #pragma unroll 1
    for (int kb = 0; kb < 12; kb++){
        int cur = kb & 1;
        if (kb < 11){
            int k0 = (kb + 1) * 16;
            ra0 = *(const float4*)(A + (size_t)am*DM + k0 + kq);
            ra1 = *(const float4*)(A + (size_t)am*DM + k0 + kq + 4);
            rb0 = *(const float4*)(g_Wt + (size_t)(k0 + bk)*WTS + e0 + bj);
            rb1 = *(const float4*)(g_Wt + (size_t)(k0 + bk + 8)*WTS + e0 + bj);
        }
        #pragma unroll
        for (int k = 0; k < 16; k++){
            float4 av0 = *(const float4*)&As[cur][k][ty*4];
            float4 av1 = *(const float4*)&As[cur][k][ty*4 + 64];
            float4 bv0 = *(const float4*)&Bs[cur][k][tx*4];
            float4 bv1 = *(const float4*)&Bs[cur][k][tx*4 + 64];
            float ar[8] = {av0.x, av0.y, av0.z, av0.w, av1.x, av1.y, av1.z, av1.w};
            float br[8] = {bv0.x, bv0.y, bv0.z, bv0.w, bv1.x, bv1.y, bv1.z, bv1.w};
            #pragma unroll
            for (int i = 0; i < 8; i++)
                #pragma unroll
                for (int j = 0; j < 8; j++)
                    acc[i][j] += ar[i]*br[j];
        }
        if (kb < 11){
            int nxt = cur ^ 1;
            As[nxt][kq+0][am] = ra0.x; As[nxt][kq+1][am] = ra0.y;
            As[nxt][kq+2][am] = ra0.z; As[nxt][kq+3][am] = ra0.w;
            As[nxt][kq+4][am] = ra1.x; As[nxt][kq+5][am] = ra1.y;
            As[nxt][kq+6][am] = ra1.z; As[nxt][kq+7][am] = ra1.w;
            *(float4*)&Bs[nxt][bk][bj]   = rb0;
            *(float4*)&Bs[nxt][bk+8][bj] = rb1;
            __syncthreads();
        }
    }

    float bias[8];
    #pragma unroll
    for (int j = 0; j < 8; j++){
        int e = e0 + tx*4 + (j >> 2)*64 + (j & 3);
        bias[j] = (e < NEP) ? g_peproj[t*NEP + e] : 0.f;
    }
    #pragma unroll
    for (int i = 0; i < 8; i++){
        int s = ty*4 + (i >> 2)*64 + (i & 3);
        float* dst = g_projR + ((size_t)bt*128 + s)*NEP;
        int eA = e0 + tx*4;
        if (eA < NEP){
            float4 v = make_float4(acc[i][0]+bias[0], acc[i][1]+bias[1],
                                   acc[i][2]+bias[2], acc[i][3]+bias[3]);
            *(float4*)(dst + eA) = v;
        }
        int eB = e0 + tx*4 + 64;
        if (eB < NEP){
            float4 v = make_float4(acc[i][4]+bias[4], acc[i][5]+bias[5],
                                   acc[i][6]+bias[6], acc[i][7]+bias[7]);
            *(float4*)(dst + eB) = v;
        }
    }
}

// ---- per-(b,h) scan: parallel within-chunk suffix scan, fp64 across chunks ----
__global__ void __launch_bounds__(128) k_scan(const float* __restrict__ dt_bias,
                                              const float* __restrict__ A_log){
    int b = blockIdx.x / NH, h = blockIdx.x % NH;
    int tid = threadIdx.x;
    float db = dt_bias[h];
    float nA = expf(A_log[h]);
    float dtv[8], ldv[8], v[8];
    #pragma unroll
    for (int t = 0; t < 8; t++){
        float z = g_projR[(((size_t)(b*8 + t))*128 + tid)*NEP + 896 + h] + db;
        float dt = softplus_f(z);
        dtv[t] = dt;
        ldv[t] = -nA*dt;
        v[t] = ldv[t];
    }
    __shared__ float sm[128][9];
    #pragma unroll
    for (int off = 1; off < 128; off <<= 1){
        __syncthreads();
        #pragma unroll
        for (int t = 0; t < 8; t++) sm[tid][t] = v[t];
        __syncthreads();
        if (tid + off < 128){
            #pragma unroll
            for (int t = 0; t < 8; t++) v[t] += sm[tid + off][t];
        }
    }
    float excl[8];
    #pragma unroll
    for (int t = 0; t < 8; t++) excl[t] = v[t] - ldv[t];
    __shared__ float totsh[8];
    if (tid == 0){
        #pragma unroll
        for (int t = 0; t < 8; t++) totsh[t] = v[t];
    }
    __syncthreads();
    float ldp[8], dtp[8];
    #pragma unroll
    for (int t = 0; t < 8; t++){ ldp[t] = g_ldpad[t*NH + h]; dtp[t] = g_dtpad[t*NH + h]; }
    double Gt[8];
    Gt[7] = 0.0;
    #pragma unroll
    for (int t = 6; t >= 0; t--)
        Gt[t] = Gt[t+1] + (double)totsh[t+1] + 128.0*(double)ldp[t+1];
    size_t wbase = (size_t)(b*NH + h)*LT;
    #pragma unroll
    for (int t = 0; t < 8; t++){
        float tail = excl[t] + 128.f*ldp[t] + (float)Gt[t];
        g_w[wbase + t*256 + tid] = dtv[t]*expf(tail);
        if (tid == 2) g_tail2[(b*NH + h)*NT + t] = tail;
    }
    if (tid < 16){
        int s = 128 + tid;
        #pragma unroll
        for (int t = 0; t < 8; t++)
            g_w[wbase + t*256 + s] = dtp[t]*expf((float)(255 - s)*ldp[t] + (float)Gt[t]);
    }
    if (tid < 8){
        int t = tid;
        double ld = (double)ldp[t];
        double geo = expm1(125.0*ld)/expm1(ld);
        g_wsum[(b*8 + t)*NH + h] = (float)((double)dtp[t]*exp(Gt[t])*geo);
    }
}

// ---- fused conv(4)+silu + head-combine, register rolling windows, 16 l per block ----
__global__ void __launch_bounds__(256) k_convy(const float* __restrict__ conv_w,
                                               const float* __restrict__ conv_b){
    int blk = blockIdx.x;
    int bt = blk / 9, j9 = blk - bt*9;
    int b = bt >> 3, t = bt & 7;
    int l0 = t*256 + j9*16;
    int tid = threadIdx.x;
    __shared__ float wsm[16][NH];
    __shared__ float ypart[256][17];
    for (int i = tid; i < 16*NH; i += 256){
        int l = i / NH, h = i - l*NH;
        wsm[l][h] = g_w[((size_t)(b*NH + h))*LT + l0 + l];
    }
    int c0 = tid, c1 = tid + 256, c2 = tid + 512, cB = 768 + (tid & 127);
    float4 w0 = *(const float4*)(conv_w + (size_t)c0*4);
    float4 w1 = *(const float4*)(conv_w + (size_t)c1*4);
    float4 w2 = *(const float4*)(conv_w + (size_t)c2*4);
    float cb0 = conv_b[c0], cb1 = conv_b[c1], cb2 = conv_b[c2];
    float4 wB = make_float4(0.f,0.f,0.f,0.f); float cbB = 0.f;
    bool doB = (tid < 128);
    if (doB){ wB = *(const float4*)(conv_w + (size_t)cB*4); cbB = conv_b[cB]; }
    int h0 = tid >> 5;
    float u0[4], u1[4], u2[4], uB[4];
    #pragma unroll
    for (int k = 1; k < 4; k++){
        int gl = l0 - 4 + k;
        bool ok = (gl >= 0);
        u0[k] = ok ? ld_proj(b, gl, c0) : 0.f;
        u1[k] = ok ? ld_proj(b, gl, c1) : 0.f;
        u2[k] = ok ? ld_proj(b, gl, c2) : 0.f;
        uB[k] = (ok && doB) ? ld_proj(b, gl, cB) : 0.f;
    }
    __syncthreads();
    float yl[16];
    #pragma unroll
    for (int j = 0; j < 16; j++){
        int gl = l0 + j;
        u0[0]=u0[1]; u0[1]=u0[2]; u0[2]=u0[3]; u0[3]=ld_proj(b, gl, c0);
        u1[0]=u1[1]; u1[1]=u1[2]; u1[2]=u1[3]; u1[3]=ld_proj(b, gl, c1);
        u2[0]=u2[1]; u2[1]=u2[2]; u2[2]=u2[3]; u2[3]=ld_proj(b, gl, c2);
        uB[0]=uB[1]; uB[1]=uB[2]; uB[2]=uB[3]; uB[3]=doB ? ld_proj(b, gl, cB) : 0.f;
        float v0 = cb0 + u0[0]*w0.x + u0[1]*w0.y + u0[2]*w0.z + u0[3]*w0.w;
        float v1 = cb1 + u1[0]*w1.x + u1[1]*w1.y + u1[2]*w1.z + u1[3]*w1.w;
        float v2 = cb2 + u2[0]*w2.x + u2[1]*w2.y + u2[2]*w2.z + u2[3]*w2.w;
        yl[j] = silu_f(v0)*wsm[j][h0] + silu_f(v1)*wsm[j][h0+8] + silu_f(v2)*wsm[j][h0+16];
        if (doB){
            float vB = cbB + uB[0]*wB.x + uB[1]*wB.y + uB[2]*wB.z + uB[3]*wB.w;
            g_B[((size_t)b*LT + gl)*DS + (tid & 127)] = silu_f(vB);
        }
    }
    #pragma unroll
    for (int j = 0; j < 16; j++) ypart[tid][j] = yl[j];
    __syncthreads();
    #pragma unroll
    for (int half = 0; half < 2; half++){
        int l = half*8 + (tid >> 5), p = tid & 31;
        float y = 0.f;
        #pragma unroll
        for (int g = 0; g < 8; g++) y += ypart[g*32 + p][l];
        g_y[((size_t)b*LT + l0 + l)*HD + p] = y;
    }
}

// ---- segment outer products over [256t+3, 256t+131), 2 subs of 64 ----
__global__ void __launch_bounds__(128) k_seg(){
    int idx = blockIdx.x;
    int b = idx >> 4, t = (idx >> 1) & 7, sub = idx & 1;
    int lbeg = t*256 + 3 + sub*64;
    int lend = lbeg + 64;
    int n = threadIdx.x;
    __shared__ float ysm[8][HD];
    float acc[HD];
    #pragma unroll
    for (int p = 0; p < HD; p++) acc[p] = 0.f;
    for (int l8 = lbeg; l8 < lend; l8 += 8){
        __syncthreads();
        for (int i = n; i < 8*HD; i += 128)
            ysm[i >> 5][i & 31] = g_y[((size_t)b*LT + l8 + (i >> 5))*HD + (i & 31)];
        __syncthreads();
        #pragma unroll
        for (int j = 0; j < 8; j++){
            float Bn = g_B[((size_t)b*LT + l8 + j)*DS + n];
            #pragma unroll
            for (int p = 0; p < HD; p++) acc[p] += ysm[j][p]*Bn;
        }
    }
    if (sub == 1 && t < 7){
        int lc = (t + 1)*256;
        __syncthreads();
        for (int i = n; i < 3*HD; i += 128)
            ysm[i >> 5][i & 31] = g_y[((size_t)b*LT + lc + (i >> 5))*HD + (i & 31)];
        __syncthreads();
        #pragma unroll
        for (int j = 0; j < 3; j++){
            float Bn = g_B[((size_t)b*LT + lc + j)*DS + n];
            #pragma unroll
            for (int p = 0; p < HD; p++) acc[p] += ysm[j][p]*Bn;
        }
    }
    float* Z = g_Zsub + (size_t)idx*4096;
    #pragma unroll
    for (int p = 0; p < HD; p++) Z[p*DS + n] = acc[p];
}

// ---- per-(b,t) 3-position boundary correction ----
__global__ void __launch_bounds__(128) k_bdry(const float* __restrict__ conv_w,
                                              const float* __restrict__ conv_b,
                                              const float* __restrict__ dt_bias,
                                              const float* __restrict__ A_log){
    int b = blockIdx.x >> 3, t = blockIdx.x & 7;
    int tid = threadIdx.x;
    __shared__ float xsb[3][896];
    __shared__ float dtb[3][NH], ldb[3][NH], wjs[3][NH];
    __shared__ float ysh[3][HD];
    for (int c = tid; c < 896; c += 128){
        float4 wv = *(const float4*)(conv_w + (size_t)c*4);
        float w[4] = {wv.x, wv.y, wv.z, wv.w};
        float cb = conv_b[c];
        #pragma unroll
        for (int j = 0; j < 3; j++){
            float v = cb;
            for (int k = 3-j; k <= 3; k++)
                v += g_projR[(((size_t)(b*NT + t))*128 + (j - 3 + k))*NEP + c]*w[k];
            xsb[j][c] = silu_f(v);
        }
    }
    if (tid < NH){
        int h = tid;
        float db = dt_bias[h], nA = expf(A_log[h]);
        for (int j = 0; j < 3; j++){
            float z = g_projR[(((size_t)(b*NT + t))*128 + j)*NEP + 896 + h] + db;
            float dt = softplus_f(z);
            dtb[j][h] = dt; ldb[j][h] = -nA*dt;
        }
    }
    __syncthreads();
    if (tid < NH){
        int h = tid;
        float t2 = g_tail2[(b*NH + h)*NT + t];
        wjs[2][h] = dtb[2][h]*expf(t2);
        float t1 = t2 + ldb[2][h];
        wjs[1][h] = dtb[1][h]*expf(t1);
        float t0 = t1 + ldb[1][h];
        wjs[0][h] = dtb[0][h]*expf(t0);
    }
    __syncthreads();
    if (tid < 96){
        int j = tid >> 5, p = tid & 31;
        float y = 0.f;
        #pragma unroll
        for (int h = 0; h < NH; h++) y += wjs[j][h]*xsb[j][h*HD + p];
        ysh[j][p] = y;
    }
    __syncthreads();
    int n = tid;
    float B0 = xsb[0][768+n], B1 = xsb[1][768+n], B2 = xsb[2][768+n];
    float* C = g_C + (size_t)blockIdx.x*4096;
    #pragma unroll
    for (int p = 0; p < HD; p++)
        C[p*DS + n] = ysh[0][p]*B0 + ysh[1][p]*B1 + ysh[2][p]*B2;
}

// ---- suffix-sum segments + rank-1 pad term + boundary corrections ----
__global__ void __launch_bounds__(256) k_finalS(){
    int b = blockIdx.x;
    int tid = threadIdx.x;
    __shared__ float ysh[8][32];
    {
        int t = tid >> 5, p = tid & 31;
        float s = 0.f;
        #pragma unroll
        for (int h = 0; h < NH; h++)
            s += g_wsum[(b*8 + t)*NH + h]*g_xc[t*896 + h*HD + p];
        ysh[t][p] = s;
    }
    __syncthreads();
    int i = blockIdx.y*256 + tid;
    int p = i >> 7, n = i & 127;
    float run = 0.f;
    for (int t = 7; t >= 0; t--){
        size_t zb = ((size_t)(b*8 + t))*2*4096 + i;
        run += g_Zsub[zb] + g_Zsub[zb + 4096] + ysh[t][p]*g_xc[t*896 + 768 + n];
        g_S[(size_t)(b*8 + t)*4096 + i] = run + g_C[(size_t)(b*8 + t)*4096 + i];
    }
}

// ---- classifier GEMM, split-K ----
__global__ void __launch_bounds__(256) k_cls(const float* __restrict__ cls_w){
    int m0 = blockIdx.x*32, n0 = blockIdx.y*32;
    int kz0 = blockIdx.z*512;
    __shared__ float As[32][33], Bs[32][33];
    int tid = threadIdx.x;
    int tx = tid & 15, ty = tid >> 4;
    int am = tid >> 3, aq = (tid & 7)*4;
    float acc00 = 0, acc01 = 0, acc10 = 0, acc11 = 0;
    bool bvalid = (n0 + am) < 100;
    for (int k0 = kz0; k0 < kz0 + 512; k0 += 32){
        float4 av = *reinterpret_cast<const float4*>(g_S + (size_t)(m0 + am)*4096 + k0 + aq);
        float4 bv = bvalid ? *reinterpret_cast<const float4*>(cls_w + (size_t)(n0 + am)*4096 + k0 + aq)
                           : make_float4(0.f, 0.f, 0.f, 0.f);
        __syncthreads();
        As[am][aq+0] = av.x; As[am][aq+1] = av.y; As[am][aq+2] = av.z; As[am][aq+3] = av.w;
        Bs[aq+0][am] = bv.x; Bs[aq+1][am] = bv.y; Bs[aq+2][am] = bv.z; Bs[aq+3][am] = bv.w;
        __syncthreads();
        #pragma unroll
        for (int k = 0; k < 32; k++){
            float a0 = As[ty*2][k],   a1 = As[ty*2+1][k];
            float b0 = Bs[k][tx*2],   b1 = Bs[k][tx*2+1];
            acc00 += a0*b0; acc01 += a0*b1; acc10 += a1*b0; acc11 += a1*b1;
        }
    }
    int m = m0 + ty*2, n = n0 + tx*2;
    float* P = g_part + (size_t)blockIdx.z*12800;
    if (n < 100)    { P[m*100 + n]     = acc00; P[(m+1)*100 + n]     = acc10; }
    if (n + 1 < 100){ P[m*100 + n + 1] = acc01; P[(m+1)*100 + n + 1] = acc11; }
}

__global__ void k_out(const float* __restrict__ cls_b, float* __restrict__ out){
    int i = blockIdx.x*blockDim.x + threadIdx.x;
    if (i >= 12800) return;
    int k = i % 100;
    float s = cls_b[k];
    #pragma unroll
    for (int z = 0; z < 8; z++) s += g_part[z*12800 + i];
    out[i] = s;
}

extern "C" void kernel_launch(void* const* d_in, const int* in_sizes, int n_in,
                              void* d_out, int out_size){
    const float* inputs    = (const float*)d_in[0];
    const float* in_proj_w = (const float*)d_in[1];
    const float* conv_w    = (const float*)d_in[2];
    const float* conv_b    = (const float*)d_in[3];
    const float* dt_bias   = (const float*)d_in[4];
    const float* A_log     = (const float*)d_in[5];
    const float* cls_w     = (const float*)d_in[6];
    const float* cls_b     = (const float*)d_in[7];
    float* out = (float*)d_out;

    k_wt<<<768, 256>>>(in_proj_w);
    k_peproj<<<8, 256>>>(in_proj_w);
    k_xc<<<8, 256>>>(conv_w, conv_b, dt_bias, A_log);
    k_gemm<<<dim3(128, 8), 256>>>(inputs);
    k_scan<<<16*24, 128>>>(dt_bias, A_log);
    k_convy<<<128*9, 256>>>(conv_w, conv_b);
    k_seg<<<256, 128>>>();
    k_bdry<<<128, 128>>>(conv_w, conv_b, dt_bias, A_log);
    k_finalS<<<dim3(16, 16), 256>>>();
    k_cls<<<dim3(4, 4, 8), 256>>>(cls_w);
    k_out<<<50, 256>>>(cls_b, out);
}

// round 12
// speedup vs baseline: 1.4359x; 1.0309x over previous
#include <cuda_runtime.h>
#include <cuda_bf16.h>
#include <math.h>

#define NB 16
#define NT 8
#define LT 2048
#define NEP 920
#define WTS 1024
#define NH 24
#define HD 32
#define DS 128
#define DM 192

__device__ float g_projR[(size_t)NB*NT*128*NEP];
__device__ float g_dtT[(size_t)NB*NH*NT*128];    // [b][h][t][s] transposed dt_raw
__device__ float g_y[(size_t)NB*LT*HD];
__device__ float g_B[(size_t)NB*LT*DS];
__device__ float g_w[(size_t)NB*NH*LT];          // [b][h][l]
__device__ float g_tail2[NB*NH*NT];
__device__ float g_wsum[NB*NT*NH];
__device__ float g_Zsub[NB*8*2*4096];
__device__ float g_C[NB*8*4096];
__device__ float g_S[NB*8*4096];
__device__ float g_part[8*128*100];
__device__ float g_Wt[192*WTS];
__device__ float g_peproj[8*NEP];
__device__ float g_xc[8*896];
__device__ float g_dtpad[8*NH];
__device__ float g_ldpad[8*NH];

__device__ __forceinline__ float softplus_f(float z){
    return log1pf(expf(-fabsf(z))) + fmaxf(z, 0.f);
}
__device__ __forceinline__ float silu_f(float v){
    return v / (1.f + expf(-v));
}
__device__ __forceinline__ int wrow_of(int ce){
    return (ce < 896) ? (768 + ce) : (896 + ce);
}
__device__ __forceinline__ float ld_proj(int b, int l, int e){
    int r = l & 255;
    if (r >= 128) return g_peproj[(l >> 8)*NEP + e];
    return g_projR[(((size_t)b*NT + (l >> 8))*128 + r)*NEP + e];
}

// ---- coalesced transpose of W (needed cols only) into [k][e], zero pad to WTS ----
__global__ void k_wt(const float* __restrict__ in_proj_w){
    __shared__ float tile[32][33];
    int e0 = blockIdx.x*32;
    int k0 = blockIdx.y*32;
    int tx = threadIdx.x, ty = threadIdx.y;     // (32, 8)
    #pragma unroll
    for (int r = 0; r < 4; r++){
        int e = e0 + ty + r*8;
        tile[ty + r*8][tx] = (e < NEP) ? in_proj_w[(size_t)wrow_of(e)*DM + k0 + tx] : 0.f;
    }
    __syncthreads();
    #pragma unroll
    for (int r = 0; r < 4; r++){
        int k = k0 + ty + r*8;
        g_Wt[(size_t)k*WTS + e0 + tx] = tile[tx][ty + r*8];
    }
}

// ---- positional encoding rows projected through W ----
__global__ void k_peproj(const float* __restrict__ in_proj_w){
    __shared__ float pe[DM];
    int t = blockIdx.x;
    int tid = threadIdx.x;
    if (tid < DM){
        float expo = -(float)(tid & ~1) * (logf(10000.0f)/(float)DM);
        float div = expf(expo);
        float ang = (float)t * div;
        pe[tid] = (tid & 1) ? cosf(ang) : sinf(ang);
    }
    __syncthreads();
    for (int e = tid; e < NEP; e += blockDim.x){
        const float* wr = in_proj_w + (size_t)wrow_of(e)*DM;
        float s = 0.f;
        for (int d = 0; d < DM; d++) s += pe[d]*wr[d];
        g_peproj[t*NEP + e] = s;
    }
}

// ---- const-pad conv+silu per t, pad dt/logdA per (t,h) ----
__global__ void k_xc(const float* __restrict__ conv_w, const float* __restrict__ conv_b,
                     const float* __restrict__ dt_bias, const float* __restrict__ A_log){
    int t = blockIdx.x;
    int tid = threadIdx.x;
    for (int c = tid; c < 896; c += 256){
        float4 wv = *(const float4*)(conv_w + (size_t)c*4);
        float v = conv_b[c] + g_peproj[t*NEP + c]*(wv.x + wv.y + wv.z + wv.w);
        g_xc[t*896 + c] = silu_f(v);
    }
    if (tid < NH){
        float z = g_peproj[t*NEP + 896 + tid] + dt_bias[tid];
        float dt = softplus_f(z);
        g_dtpad[t*NH + tid] = dt;
        g_ldpad[t*NH + tid] = -expf(A_log[tid])*dt;
    }
}

// ---- main GEMM: fp32 SIMT 128x128 tile, 8x8 per thread via packed f32x2 FMA ----
__global__ void __launch_bounds__(256, 2) k_gemm(const float* __restrict__ inputs){
    int bt = blockIdx.x;
    int b = bt >> 3, t = bt & 7;
    int e0 = blockIdx.y * 128;
    const float* A = inputs + ((size_t)bt*129 + 1)*DM;
    __shared__ float As[2][16][128];
    __shared__ float Bs[2][16][128];
    int tid = threadIdx.x;
    int am = tid & 127, kq = (tid >> 7) * 8;
    int bk = tid >> 5,  bj = (tid & 31) * 4;
    int ty = tid >> 4,  tx = tid & 15;

    // acc packed along j: acc2[i][jp] = {acc[i][2jp], acc[i][2jp+1]}
    unsigned long long acc2[8][4];
    #pragma unroll
    for (int i = 0; i < 8; i++)
        #pragma unroll
        for (int jp = 0; jp < 4; jp++) acc2[i][jp] = 0ull;

    float4 ra0, ra1, rb0, rb1;
    ra0 = *(const float4*)(A + (size_t)am*DM + kq);
    ra1 = *(const float4*)(A + (size_t)am*DM + kq + 4);
    rb0 = *(const float4*)(g_Wt + (size_t)bk*WTS + e0 + bj);
    rb1 = *(const float4*)(g_Wt + (size_t)(bk + 8)*WTS + e0 + bj);
    As[0][kq+0][am] = ra0.x; As[0][kq+1][am] = ra0.y; As[0][kq+2][am] = ra0.z; As[0][kq+3][am] = ra0.w;
    As[0][kq+4][am] = ra1.x; As[0][kq+5][am] = ra1.y; As[0][kq+6][am] = ra1.z; As[0][kq+7][am] = ra1.w;
    *(float4*)&Bs[0][bk][bj]     = rb0;
    *(float4*)&Bs[0][bk+8][bj]   = rb1;
    __syncthreads();

    #pragma unroll 1
    for (int kb = 0; kb < 12; kb++){
        int cur = kb & 1;
        if (kb < 11){
            int k0 = (kb + 1) * 16;
            ra0 = *(const float4*)(A + (size_t)am*DM + k0 + kq);
            ra1 = *(const float4*)(A + (size_t)am*DM + k0 + kq + 4);
            rb0 = *(const float4*)(g_Wt + (size_t)(k0 + bk)*WTS + e0 + bj);
            rb1 = *(const float4*)(g_Wt + (size_t)(k0 + bk + 8)*WTS + e0 + bj);
        }
        #pragma unroll
        for (int k = 0; k < 16; k++){
            float4 av0 = *(const float4*)&As[cur][k][ty*4];
            float4 av1 = *(const float4*)&As[cur][k][ty*4 + 64];
            float4 bv0 = *(const float4*)&Bs[cur][k][tx*4];
            float4 bv1 = *(const float4*)&Bs[cur][k][tx*4 + 64];
            unsigned long long bp[4];
            asm("mov.b64 %0, {%1, %2};" : "=l"(bp[0]) : "f"(bv0.x), "f"(bv0.y));
            asm("mov.b64 %0, {%1, %2};" : "=l"(bp[1]) : "f"(bv0.z), "f"(bv0.w));
            asm("mov.b64 %0, {%1, %2};" : "=l"(bp[2]) : "f"(bv1.x), "f"(bv1.y));
            asm("mov.b64 %0, {%1, %2};" : "=l"(bp[3]) : "f"(bv1.z), "f"(bv1.w));
            float ar[8] = {av0.x, av0.y, av0.z, av0.w, av1.x, av1.y, av1.z, av1.w};
            #pragma unroll
            for (int i = 0; i < 8; i++){
                unsigned long long ap;
                asm("mov.b64 %0, {%1, %1};" : "=l"(ap) : "f"(ar[i]));
                #pragma unroll
                for (int jp = 0; jp < 4; jp++)
                    asm("fma.rn.f32x2 %0, %1, %2, %0;" : "+l"(acc2[i][jp]) : "l"(ap), "l"(bp[jp]));
            }
        }
        if (kb < 11){
            int nxt = cur ^ 1;
            As[nxt][kq+0][am] = ra0.x; As[nxt][kq+1][am] = ra0.y;
            As[nxt][kq+2][am] = ra0.z; As[nxt][kq+3][am] = ra0.w;
            As[nxt][kq+4][am] = ra1.x; As[nxt][kq+5][am] = ra1.y;
            As[nxt][kq+6][am] = ra1.z; As[nxt][kq+7][am] = ra1.w;
            *(float4*)&Bs[nxt][bk][bj]   = rb0;
            *(float4*)&Bs[nxt][bk+8][bj] = rb1;
            __syncthreads();
        }
    }

    // unpack accumulators
    float accf[8][8];
    #pragma unroll
    for (int i = 0; i < 8; i++)
        #pragma unroll
        for (int jp = 0; jp < 4; jp++)
            asm("mov.b64 {%0, %1}, %2;" : "=f"(accf[i][2*jp]), "=f"(accf[i][2*jp+1]) : "l"(acc2[i][jp]));

    float bias[8];
    #pragma unroll
    for (int j = 0; j < 8; j++){
        int e = e0 + tx*4 + (j >> 2)*64 + (j & 3);
        bias[j] = (e < NEP) ? g_peproj[t*NEP + e] : 0.f;
    }
    bool dtTile = (e0 == 896);
    #pragma unroll
    for (int i = 0; i < 8; i++){
        int s = ty*4 + (i >> 2)*64 + (i & 3);
        float* dst = g_projR + ((size_t)bt*128 + s)*NEP;
        int eA = e0 + tx*4;
        if (eA < NEP){
            float4 v = make_float4(accf[i][0]+bias[0], accf[i][1]+bias[1],
                                   accf[i][2]+bias[2], accf[i][3]+bias[3]);
            *(float4*)(dst + eA) = v;
            if (dtTile){
                #pragma unroll
                for (int j = 0; j < 4; j++){
                    int e = eA + j;
                    if (e >= 896 && e < 920){
                        int h = e - 896;
                        g_dtT[(((size_t)(b*NH + h))*NT + t)*128 + s] = accf[i][j] + bias[j];
                    }
                }
            }
        }
        int eB = e0 + tx*4 + 64;
        if (eB < NEP){
            float4 v = make_float4(accf[i][4]+bias[4], accf[i][5]+bias[5],
                                   accf[i][6]+bias[6], accf[i][7]+bias[7]);
            *(float4*)(dst + eB) = v;
        }
    }
}

// ---- per-(b,h) scan: parallel within-chunk suffix scan, fp64 across chunks ----
__global__ void __launch_bounds__(128) k_scan(const float* __restrict__ dt_bias,
                                              const float* __restrict__ A_log){
    int b = blockIdx.x / NH, h = blockIdx.x % NH;
    int tid = threadIdx.x;
    float db = dt_bias[h];
    float nA = expf(A_log[h]);
    float dtv[8], ldv[8], v[8];
    #pragma unroll
    for (int t = 0; t < 8; t++){
        float z = g_dtT[(((size_t)(b*NH + h))*NT + t)*128 + tid] + db;
        float dt = softplus_f(z);
        dtv[t] = dt;
        ldv[t] = -nA*dt;
        v[t] = ldv[t];
    }
    __shared__ float sm[128][9];
    #pragma unroll
    for (int off = 1; off < 128; off <<= 1){
        __syncthreads();
        #pragma unroll
        for (int t = 0; t < 8; t++) sm[tid][t] = v[t];
        __syncthreads();
        if (tid + off < 128){
            #pragma unroll
            for (int t = 0; t < 8; t++) v[t] += sm[tid + off][t];
        }
    }
    float excl[8];
    #pragma unroll
    for (int t = 0; t < 8; t++) excl[t] = v[t] - ldv[t];
    __shared__ float totsh[8];
    if (tid == 0){
        #pragma unroll
        for (int t = 0; t < 8; t++) totsh[t] = v[t];
    }
    __syncthreads();
    float ldp[8], dtp[8];
    #pragma unroll
    for (int t = 0; t < 8; t++){ ldp[t] = g_ldpad[t*NH + h]; dtp[t] = g_dtpad[t*NH + h]; }
    double Gt[8];
    Gt[7] = 0.0;
    #pragma unroll
    for (int t = 6; t >= 0; t--)
        Gt[t] = Gt[t+1] + (double)totsh[t+1] + 128.0*(double)ldp[t+1];
    size_t wbase = (size_t)(b*NH + h)*LT;
    #pragma unroll
    for (int t = 0; t < 8; t++){
        float tail = excl[t] + 128.f*ldp[t] + (float)Gt[t];
        g_w[wbase + t*256 + tid] = dtv[t]*expf(tail);
        if (tid == 2) g_tail2[(b*NH + h)*NT + t] = tail;
    }
    if (tid < 16){
        int s = 128 + tid;
        #pragma unroll
        for (int t = 0; t < 8; t++)
            g_w[wbase + t*256 + s] = dtp[t]*expf((float)(255 - s)*ldp[t] + (float)Gt[t]);
    }
    if (tid < 8){
        int t = tid;
        double ld = (double)ldp[t];
        double geo = expm1(125.0*ld)/expm1(ld);
        g_wsum[(b*8 + t)*NH + h] = (float)((double)dtp[t]*exp(Gt[t])*geo);
    }
}

// ---- fused conv(4)+silu + head-combine, register rolling windows, 16 l per block ----
__global__ void __launch_bounds__(256) k_convy(const float* __restrict__ conv_w,
                                               const float* __restrict__ conv_b){
    int blk = blockIdx.x;
    int bt = blk / 9, j9 = blk - bt*9;
    int b = bt >> 3, t = bt & 7;
    int l0 = t*256 + j9*16;
    int tid = threadIdx.x;
    __shared__ float wsm[16][NH];
    __shared__ float ypart[256][17];
    for (int i = tid; i < 16*NH; i += 256){
        int l = i / NH, h = i - l*NH;
        wsm[l][h] = g_w[((size_t)(b*NH + h))*LT + l0 + l];
    }
    int c0 = tid, c1 = tid + 256, c2 = tid + 512, cB = 768 + (tid & 127);
    float4 w0 = *(const float4*)(conv_w + (size_t)c0*4);
    float4 w1 = *(const float4*)(conv_w + (size_t)c1*4);
    float4 w2 = *(const float4*)(conv_w + (size_t)c2*4);
    float cb0 = conv_b[c0], cb1 = conv_b[c1], cb2 = conv_b[c2];
    float4 wB = make_float4(0.f,0.f,0.f,0.f); float cbB = 0.f;
    bool doB = (tid < 128);
    if (doB){ wB = *(const float4*)(conv_w + (size_t)cB*4); cbB = conv_b[cB]; }
    int h0 = tid >> 5;
    float u0[4], u1[4], u2[4], uB[4];
    #pragma unroll
    for (int k = 1; k < 4; k++){
        int gl = l0 - 4 + k;
        bool ok = (gl >= 0);
        u0[k] = ok ? ld_proj(b, gl, c0) : 0.f;
        u1[k] = ok ? ld_proj(b, gl, c1) : 0.f;
        u2[k] = ok ? ld_proj(b, gl, c2) : 0.f;
        uB[k] = (ok && doB) ? ld_proj(b, gl, cB) : 0.f;
    }
    __syncthreads();
    float yl[16];
    #pragma unroll
    for (int j = 0; j < 16; j++){
        int gl = l0 + j;
        u0[0]=u0[1]; u0[1]=u0[2]; u0[2]=u0[3]; u0[3]=ld_proj(b, gl, c0);
        u1[0]=u1[1]; u1[1]=u1[2]; u1[2]=u1[3]; u1[3]=ld_proj(b, gl, c1);
        u2[0]=u2[1]; u2[1]=u2[2]; u2[2]=u2[3]; u2[3]=ld_proj(b, gl, c2);
        uB[0]=uB[1]; uB[1]=uB[2]; uB[2]=uB[3]; uB[3]=doB ? ld_proj(b, gl, cB) : 0.f;
        float v0 = cb0 + u0[0]*w0.x + u0[1]*w0.y + u0[2]*w0.z + u0[3]*w0.w;
        float v1 = cb1 + u1[0]*w1.x + u1[1]*w1.y + u1[2]*w1.z + u1[3]*w1.w;
        float v2 = cb2 + u2[0]*w2.x + u2[1]*w2.y + u2[2]*w2.z + u2[3]*w2.w;
        yl[j] = silu_f(v0)*wsm[j][h0] + silu_f(v1)*wsm[j][h0+8] + silu_f(v2)*wsm[j][h0+16];
        if (doB){
            float vB = cbB + uB[0]*wB.x + uB[1]*wB.y + uB[2]*wB.z + uB[3]*wB.w;
            g_B[((size_t)b*LT + gl)*DS + (tid & 127)] = silu_f(vB);
        }
    }
    #pragma unroll
    for (int j = 0; j < 16; j++) ypart[tid][j] = yl[j];
    __syncthreads();
    #pragma unroll
    for (int half = 0; half < 2; half++){
        int l = half*8 + (tid >> 5), p = tid & 31;
        float y = 0.f;
        #pragma unroll
        for (int g = 0; g < 8; g++) y += ypart[g*32 + p][l];
        g_y[((size_t)b*LT + l0 + l)*HD + p] = y;
    }
}

// ---- segment outer products over [256t+3, 256t+131), 2 subs of 64 ----
__global__ void __launch_bounds__(128) k_seg(){
    int idx = blockIdx.x;
    int b = idx >> 4, t = (idx >> 1) & 7, sub = idx & 1;
    int lbeg = t*256 + 3 + sub*64;
    int lend = lbeg + 64;
    int n = threadIdx.x;
    __shared__ float ysm[8][HD];
    float acc[HD];
    #pragma unroll
    for (int p = 0; p < HD; p++) acc[p] = 0.f;
    for (int l8 = lbeg; l8 < lend; l8 += 8){
        __syncthreads();
        for (int i = n; i < 8*HD; i += 128)
            ysm[i >> 5][i & 31] = g_y[((size_t)b*LT + l8 + (i >> 5))*HD + (i & 31)];
        __syncthreads();
        #pragma unroll
        for (int j = 0; j < 8; j++){
            float Bn = g_B[((size_t)b*LT + l8 + j)*DS + n];
            #pragma unroll
            for (int p = 0; p < HD; p++) acc[p] += ysm[j][p]*Bn;
        }
    }
    if (sub == 1 && t < 7){
        int lc = (t + 1)*256;
        __syncthreads();
        for (int i = n; i < 3*HD; i += 128)
            ysm[i >> 5][i & 31] = g_y[((size_t)b*LT + lc + (i >> 5))*HD + (i & 31)];
        __syncthreads();
        #pragma unroll
        for (int j = 0; j < 3; j++){
            float Bn = g_B[((size_t)b*LT + lc + j)*DS + n];
            #pragma unroll
            for (int p = 0; p < HD; p++) acc[p] += ysm[j][p]*Bn;
        }
    }
    float* Z = g_Zsub + (size_t)idx*4096;
    #pragma unroll
    for (int p = 0; p < HD; p++) Z[p*DS + n] = acc[p];
}

// ---- per-(b,t) 3-position boundary correction ----
__global__ void __launch_bounds__(128) k_bdry(const float* __restrict__ conv_w,
                                              const float* __restrict__ conv_b,
                                              const float* __restrict__ dt_bias,
                                              const float* __restrict__ A_log){
    int b = blockIdx.x >> 3, t = blockIdx.x & 7;
    int tid = threadIdx.x;
    __shared__ float xsb[3][896];
    __shared__ float dtb[3][NH], ldb[3][NH], wjs[3][NH];
    __shared__ float ysh[3][HD];
    for (int c = tid; c < 896; c += 128){
        float4 wv = *(const float4*)(conv_w + (size_t)c*4);
        float w[4] = {wv.x, wv.y, wv.z, wv.w};
        float cb = conv_b[c];
        #pragma unroll
        for (int j = 0; j < 3; j++){
            float v = cb;
            for (int k = 3-j; k <= 3; k++)
                v += g_projR[(((size_t)(b*NT + t))*128 + (j - 3 + k))*NEP + c]*w[k];
            xsb[j][c] = silu_f(v);
        }
    }
    if (tid < NH){
        int h = tid;
        float db = dt_bias[h], nA = expf(A_log[h]);
        for (int j = 0; j < 3; j++){
            float z = g_projR[(((size_t)(b*NT + t))*128 + j)*NEP + 896 + h] + db;
            float dt = softplus_f(z);
            dtb[j][h] = dt; ldb[j][h] = -nA*dt;
        }
    }
    __syncthreads();
    if (tid < NH){
        int h = tid;
        float t2 = g_tail2[(b*NH + h)*NT + t];
        wjs[2][h] = dtb[2][h]*expf(t2);
        float t1 = t2 + ldb[2][h];
        wjs[1][h] = dtb[1][h]*expf(t1);
        float t0 = t1 + ldb[1][h];
        wjs[0][h] = dtb[0][h]*expf(t0);
    }
    __syncthreads();
    if (tid < 96){
        int j = tid >> 5, p = tid & 31;
        float y = 0.f;
        #pragma unroll
        for (int h = 0; h < NH; h++) y += wjs[j][h]*xsb[j][h*HD + p];
        ysh[j][p] = y;
    }
    __syncthreads();
    int n = tid;
    float B0 = xsb[0][768+n], B1 = xsb[1][768+n], B2 = xsb[2][768+n];
    float* C = g_C + (size_t)blockIdx.x*4096;
    #pragma unroll
    for (int p = 0; p < HD; p++)
        C[p*DS + n] = ysh[0][p]*B0 + ysh[1][p]*B1 + ysh[2][p]*B2;
}

// ---- suffix-sum segments + rank-1 pad term + boundary corrections ----
__global__ void __launch_bounds__(256) k_finalS(){
    int b = blockIdx.x;
    int tid = threadIdx.x;
    __shared__ float ysh[8][32];
    {
        int t = tid >> 5, p = tid & 31;
        float s = 0.f;
        #pragma unroll
        for (int h = 0; h < NH; h++)
            s += g_wsum[(b*8 + t)*NH + h]*g_xc[t*896 + h*HD + p];
        ysh[t][p] = s;
    }
    __syncthreads();
    int i = blockIdx.y*256 + tid;
    int p = i >> 7, n = i & 127;
    float run = 0.f;
    for (int t = 7; t >= 0; t--){
        size_t zb = ((size_t)(b*8 + t))*2*4096 + i;
        run += g_Zsub[zb] + g_Zsub[zb + 4096] + ysh[t][p]*g_xc[t*896 + 768 + n];
        g_S[(size_t)(b*8 + t)*4096 + i] = run + g_C[(size_t)(b*8 + t)*4096 + i];
    }
}

// ---- classifier GEMM, split-K ----
__global__ void __launch_bounds__(256) k_cls(const float* __restrict__ cls_w){
    int m0 = blockIdx.x*32, n0 = blockIdx.y*32;
    int kz0 = blockIdx.z*512;
    __shared__ float As[32][33], Bs[32][33];
    int tid = threadIdx.x;
    int tx = tid & 15, ty = tid >> 4;
    int am = tid >> 3, aq = (tid & 7)*4;
    float acc00 = 0, acc01 = 0, acc10 = 0, acc11 = 0;
    bool bvalid = (n0 + am) < 100;
    for (int k0 = kz0; k0 < kz0 + 512; k0 += 32){
        float4 av = *reinterpret_cast<const float4*>(g_S + (size_t)(m0 + am)*4096 + k0 + aq);
        float4 bv = bvalid ? *reinterpret_cast<const float4*>(cls_w + (size_t)(n0 + am)*4096 + k0 + aq)
                           : make_float4(0.f, 0.f, 0.f, 0.f);
        __syncthreads();
        As[am][aq+0] = av.x; As[am][aq+1] = av.y; As[am][aq+2] = av.z; As[am][aq+3] = av.w;
        Bs[aq+0][am] = bv.x; Bs[aq+1][am] = bv.y; Bs[aq+2][am] = bv.z; Bs[aq+3][am] = bv.w;
        __syncthreads();
        #pragma unroll
        for (int k = 0; k < 32; k++){
            float a0 = As[ty*2][k],   a1 = As[ty*2+1][k];
            float b0 = Bs[k][tx*2],   b1 = Bs[k][tx*2+1];
            acc00 += a0*b0; acc01 += a0*b1; acc10 += a1*b0; acc11 += a1*b1;
        }
    }
    int m = m0 + ty*2, n = n0 + tx*2;
    float* P = g_part + (size_t)blockIdx.z*12800;
    if (n < 100)    { P[m*100 + n]     = acc00; P[(m+1)*100 + n]     = acc10; }
    if (n + 1 < 100){ P[m*100 + n + 1] = acc01; P[(m+1)*100 + n + 1] = acc11; }
}

__global__ void k_out(const float* __restrict__ cls_b, float* __restrict__ out){
    int i = blockIdx.x*blockDim.x + threadIdx.x;
    if (i >= 12800) return;
    int k = i % 100;
    float s = cls_b[k];
    #pragma unroll
    for (int z = 0; z < 8; z++) s += g_part[z*12800 + i];
    out[i] = s;
}

extern "C" void kernel_launch(void* const* d_in, const int* in_sizes, int n_in,
                              void* d_out, int out_size){
    const float* inputs    = (const float*)d_in[0];
    const float* in_proj_w = (const float*)d_in[1];
    const float* conv_w    = (const float*)d_in[2];
    const float* conv_b    = (const float*)d_in[3];
    const float* dt_bias   = (const float*)d_in[4];
    const float* A_log     = (const float*)d_in[5];
    const float* cls_w     = (const float*)d_in[6];
    const float* cls_b     = (const float*)d_in[7];
    float* out = (float*)d_out;

    k_wt<<<dim3(32, 6), dim3(32, 8)>>>(in_proj_w);
    k_peproj<<<8, 256>>>(in_proj_w);
    k_xc<<<8, 256>>>(conv_w, conv_b, dt_bias, A_log);
    k_gemm<<<dim3(128, 8), 256>>>(inputs);
    k_scan<<<16*24, 128>>>(dt_bias, A_log);
    k_convy<<<128*9, 256>>>(conv_w, conv_b);
    k_seg<<<256, 128>>>();
    k_bdry<<<128, 128>>>(conv_w, conv_b, dt_bias, A_log);
    k_finalS<<<dim3(16, 16), 256>>>();
    k_cls<<<dim3(4, 4, 8), 256>>>(cls_w);
    k_out<<<50, 256>>>(cls_b, out);
}